// round 13
// baseline (speedup 1.0000x reference)
#include <cuda_runtime.h>

static const int FR = 8 * 64 * 64 * 64;  // B*H*W*F = 2097152 floats per state frame

// Scratch (device globals -- no allocation allowed)
__device__ float g_hist0[10ull * 2097152];
__device__ float g_hist1[10ull * 2097152];
__device__ float g_c0[2097152];
__device__ float g_c1[2097152];

typedef unsigned long long ull;

__device__ __forceinline__ ull pack2(float a) {
    ull r; asm("mov.b64 %0, {%1, %1};" : "=l"(r) : "f"(a)); return r;
}
__device__ __forceinline__ void fma2(ull& d, ull a, ull b) {
    asm("fma.rn.f32x2 %0, %1, %2, %0;" : "+l"(d) : "l"(a), "l"(b));
}
__device__ __forceinline__ float2 unpk(ull v) {
    float2 f; asm("mov.b64 {%0, %1}, %2;" : "=f"(f.x), "=f"(f.y) : "l"(v)); return f;
}
__device__ __forceinline__ float hsig(float x) { return __saturatef(fmaf(0.2f, x, 0.5f)); }

// Load [3 rows][66 cols][64 ch] halo tile transposed to smem [dy][cin][66].
__device__ __forceinline__ void load_tile64(float* __restrict__ s,
                                            const float* __restrict__ frame,
                                            int h, int tid)
{
    for (int idx = tid; idx < 3 * 66 * 16; idx += 256) {
        int c4 = idx & 15;
        int colr = idx >> 4;
        int col = colr % 66;
        int dy = colr / 66;
        int row = h + dy - 1;
        int win = col - 1;
        float4 v = make_float4(0.f, 0.f, 0.f, 0.f);
        if ((unsigned)row < 64u && (unsigned)win < 64u)
            v = *(const float4*)&frame[(row * 64 + win) * 64 + c4 * 4];
        int base = (dy * 64 + c4 * 4) * 66 + col;
        s[base]       = v.x;
        s[base + 66]  = v.y;
        s[base + 132] = v.z;
        s[base + 198] = v.w;
    }
}

// One 3x3 conv contribution with CIN=64: acc += conv(sIn, gw).
// 16-row chunks, 2 barriers/chunk, 4096-float sW. Warp covers 8 tn x 4 tw
// (set by caller's index map) -> each B LDS.128 = 8 distinct contiguous 16B
// = 1 crossbar wavefront; each A scalar LDS = 4 words, 8-way bcast = 1 wf.
// sIn: smem [3][64][66]; gw: global weights [9*64][256] K-major.
__device__ __forceinline__ void conv_part64(ull acc[4][4][2],
                                            const float* __restrict__ sIn,
                                            const float* __restrict__ gw,
                                            float* __restrict__ sW,
                                            int tid, int tw, int n0)
{
    for (int tap = 0; tap < 9; ++tap) {
        const float* sbase = sIn + (tap / 3) * (64 * 66) + (tap % 3);
        const float4* wsrc = (const float4*)(gw + tap * 64 * 256);
        for (int ch = 0; ch < 4; ++ch) {
            __syncthreads();   // also orders callers' sIn writes before first compute
            float4* dst = (float4*)sW;
#pragma unroll
            for (int i = 0; i < 4; ++i)
                dst[tid + i * 256] = wsrc[ch * 1024 + tid + i * 256];
            __syncthreads();
#pragma unroll
            for (int kk = 0; kk < 16; ++kk) {
                const float* a = sbase + (ch * 16 + kk) * 66;
                ull aa0 = pack2(a[tw]);
                ull aa1 = pack2(a[tw + 16]);
                ull aa2 = pack2(a[tw + 32]);
                ull aa3 = pack2(a[tw + 48]);
                const float* brow = sW + kk * 256 + n0;
#pragma unroll
                for (int g = 0; g < 4; ++g) {
                    ulonglong2 bb = *(const ulonglong2*)(brow + g * 64);
                    fma2(acc[0][g][0], aa0, bb.x); fma2(acc[0][g][1], aa0, bb.y);
                    fma2(acc[1][g][0], aa1, bb.x); fma2(acc[1][g][1], aa1, bb.y);
                    fma2(acc[2][g][0], aa2, bb.x); fma2(acc[2][g][1], aa2, bb.y);
                    fma2(acc[3][g][0], aa3, bb.x); fma2(acc[3][g][1], aa3, bb.y);
                }
            }
        }
    }
}

// Fused ConvLSTM step. Block = one (b,h) row: 64 w x 256 gate channels.
// Thread (tn,tw): features n0=4*tn..+3 per gate; w in {tw, tw+16, tw+32, tw+48}.
// Warp-internal map puts 8 tn-groups x 4 tw-quads in each warp (crossbar-minimal).
template <bool CIN1, bool HAS_PREV>
__global__ __launch_bounds__(256)
void step_kernel(const float* __restrict__ xin, long long xin_bstride,
                 const float* __restrict__ hprev,
                 const float* __restrict__ Wx,
                 const float* __restrict__ Wh,
                 const float* __restrict__ bias,
                 float* __restrict__ cbuf,
                 float* __restrict__ hout)
{
    extern __shared__ float smem[];
    constexpr int TILE = (CIN1 && !HAS_PREV) ? 0 : 12672;  // [3][64][66]
    constexpr int SX1  = CIN1 ? 200 : 0;                   // [3][66] + pad (16B align)
    float* sT  = smem;
    float* sX1 = smem + TILE;
    float* sW  = smem + TILE + SX1;                        // 4096 floats

    const int tid = threadIdx.x;
    const int bh = blockIdx.x;
    const int b = bh >> 6, h = bh & 63;
    const int lane = tid & 31, warp = tid >> 5;
    const int tn = (lane & 7) | ((warp & 1) << 3);         // 0..15
    const int tw = ((lane >> 3) & 3) | ((warp >> 1) << 2); // 0..15
    const int n0 = tn * 4;

    const float* xframe = xin + (long long)b * xin_bstride;

    // ---- load x tile ----
    if constexpr (CIN1) {
        for (int idx = tid; idx < 3 * 66; idx += 256) {
            int dy = idx / 66, col = idx - dy * 66;
            int row = h + dy - 1, win = col - 1;
            float v = 0.f;
            if ((unsigned)row < 64u && (unsigned)win < 64u) v = xframe[row * 64 + win];
            sX1[idx] = v;
        }
    } else {
        load_tile64(sT, xframe, h, tid);
    }

    ull acc[4][4][2];
#pragma unroll
    for (int i = 0; i < 4; i++)
#pragma unroll
        for (int g = 0; g < 4; g++) { acc[i][g][0] = 0ull; acc[i][g][1] = 0ull; }

    // ---- x-conv ----
    if constexpr (CIN1) {
        __syncthreads();
        for (int i = tid; i < 576; i += 256) ((float4*)sW)[i] = ((const float4*)Wx)[i];
        __syncthreads();
#pragma unroll
        for (int tap = 0; tap < 9; ++tap) {
            const float* arow = sX1 + (tap / 3) * 66 + (tap % 3);
            ull aa0 = pack2(arow[tw]);
            ull aa1 = pack2(arow[tw + 16]);
            ull aa2 = pack2(arow[tw + 32]);
            ull aa3 = pack2(arow[tw + 48]);
            const float* brow = sW + tap * 256 + n0;
#pragma unroll
            for (int g = 0; g < 4; ++g) {
                ulonglong2 bb = *(const ulonglong2*)(brow + g * 64);
                fma2(acc[0][g][0], aa0, bb.x); fma2(acc[0][g][1], aa0, bb.y);
                fma2(acc[1][g][0], aa1, bb.x); fma2(acc[1][g][1], aa1, bb.y);
                fma2(acc[2][g][0], aa2, bb.x); fma2(acc[2][g][1], aa2, bb.y);
                fma2(acc[3][g][0], aa3, bb.x); fma2(acc[3][g][1], aa3, bb.y);
            }
        }
    } else {
        conv_part64(acc, sT, Wx, sW, tid, tw, n0);
    }

    // ---- h-conv (reuses sT) ----
    if constexpr (HAS_PREV) {
        __syncthreads();  // x-phase reads of sT/sW complete before overwrite
        load_tile64(sT, hprev + (long long)b * (64 * 64 * 64), h, tid);
        conv_part64(acc, sT, Wh, sW, tid, tw, n0);
    }

    // ---- fused epilogue: bias + activations + state update ----
    float bg[4][4];
#pragma unroll
    for (int g = 0; g < 4; ++g) {
        float4 t = *(const float4*)(bias + g * 64 + n0);
        bg[g][0] = t.x; bg[g][1] = t.y; bg[g][2] = t.z; bg[g][3] = t.w;
    }
    const long long rowbase = (long long)bh * 4096 + n0;
#pragma unroll
    for (int i = 0; i < 4; i++) {
        long long off = rowbase + (long long)(tw + 16 * i) * 64;
        float cp[4] = {0.f, 0.f, 0.f, 0.f};
        if constexpr (HAS_PREV) {
            float4 t = *(const float4*)&cbuf[off];
            cp[0] = t.x; cp[1] = t.y; cp[2] = t.z; cp[3] = t.w;
        }
        float gv[4][4];
#pragma unroll
        for (int g = 0; g < 4; ++g) {
            float2 p0 = unpk(acc[i][g][0]);
            float2 p1 = unpk(acc[i][g][1]);
            gv[g][0] = p0.x + bg[g][0];
            gv[g][1] = p0.y + bg[g][1];
            gv[g][2] = p1.x + bg[g][2];
            gv[g][3] = p1.y + bg[g][3];
        }
        float cn[4], hn[4];
#pragma unroll
        for (int j = 0; j < 4; j++) {
            float iv = hsig(gv[0][j]);
            float fv = hsig(gv[1][j]);
            float gg = tanhf(gv[2][j]);
            float ov = hsig(gv[3][j]);
            float c = fv * cp[j] + iv * gg;
            cn[j] = c;
            hn[j] = ov * tanhf(c);
        }
        *(float4*)&cbuf[off] = make_float4(cn[0], cn[1], cn[2], cn[3]);
        *(float4*)&hout[off] = make_float4(hn[0], hn[1], hn[2], hn[3]);
    }
}

extern "C" void kernel_launch(void* const* d_in, const int* in_sizes, int n_in,
                              void* d_out, int out_size)
{
    const float* x   = (const float*)d_in[0];
    const float* Wx0 = (const float*)d_in[1];
    const float* Wh0 = (const float*)d_in[2];
    const float* b0  = (const float*)d_in[3];
    const float* Wx1 = (const float*)d_in[4];
    const float* Wh1 = (const float*)d_in[5];
    const float* b1  = (const float*)d_in[6];
    float* out = (float*)d_out;

    float *hist0, *hist1, *c0, *c1;
    cudaGetSymbolAddress((void**)&hist0, g_hist0);
    cudaGetSymbolAddress((void**)&hist1, g_hist1);
    cudaGetSymbolAddress((void**)&c0, g_c0);
    cudaGetSymbolAddress((void**)&c1, g_c1);

    const int SM_1N  = (200 + 4096) * 4;                 // 17184 B
    const int SM_1P  = (12672 + 200 + 4096) * 4;         // 67872 B
    const int SM_64N = (12672 + 4096) * 4;               // 67072 B
    const int SM_64P = (12672 + 4096) * 4;               // 67072 B
    cudaFuncSetAttribute(step_kernel<true,  false>, cudaFuncAttributeMaxDynamicSharedMemorySize, SM_1N);
    cudaFuncSetAttribute(step_kernel<true,  true>,  cudaFuncAttributeMaxDynamicSharedMemorySize, SM_1P);
    cudaFuncSetAttribute(step_kernel<false, false>, cudaFuncAttributeMaxDynamicSharedMemorySize, SM_64N);
    cudaFuncSetAttribute(step_kernel<false, true>,  cudaFuncAttributeMaxDynamicSharedMemorySize, SM_64P);

    dim3 grid(512), block(256);

    // Layer 0
    step_kernel<true, false><<<grid, block, SM_1N>>>(x, 40960LL, nullptr,
                                                     Wx0, Wh0, b0, c0, hist0);
    for (int t = 1; t < 10; ++t)
        step_kernel<true, true><<<grid, block, SM_1P>>>(x + (size_t)t * 4096, 40960LL,
                                                        hist0 + (size_t)(t - 1) * FR,
                                                        Wx0, Wh0, b0, c0,
                                                        hist0 + (size_t)t * FR);

    // Layer 1
    step_kernel<false, false><<<grid, block, SM_64N>>>(hist0, 262144LL, nullptr,
                                                       Wx1, Wh1, b1, c1, hist1);
    for (int t = 1; t < 10; ++t)
        step_kernel<false, true><<<grid, block, SM_64P>>>(hist0 + (size_t)t * FR, 262144LL,
                                                          hist1 + (size_t)(t - 1) * FR,
                                                          Wx1, Wh1, b1, c1,
                                                          hist1 + (size_t)t * FR);

    // Pack output: [[h0,c0],[h1,c1]]
    cudaMemcpyAsync(out,              hist0 + 9ull * FR, (size_t)FR * 4, cudaMemcpyDeviceToDevice);
    cudaMemcpyAsync(out + (size_t)FR, c0,                (size_t)FR * 4, cudaMemcpyDeviceToDevice);
    cudaMemcpyAsync(out + 2ull * FR,  hist1 + 9ull * FR, (size_t)FR * 4, cudaMemcpyDeviceToDevice);
    cudaMemcpyAsync(out + 3ull * FR,  c1,                (size_t)FR * 4, cudaMemcpyDeviceToDevice);
}

// round 14
// speedup vs baseline: 1.0533x; 1.0533x over previous
#include <cuda_runtime.h>

static const int FR = 8 * 64 * 64 * 64;  // B*H*W*F = 2097152 floats per state frame

// Scratch (device globals -- no allocation allowed)
__device__ float g_hist0[10ull * 2097152];
__device__ float g_hist1[10ull * 2097152];
__device__ float g_c0[2097152];
__device__ float g_c1[2097152];

typedef unsigned long long ull;

__device__ __forceinline__ ull pack2(float a) {
    ull r; asm("mov.b64 %0, {%1, %1};" : "=l"(r) : "f"(a)); return r;
}
__device__ __forceinline__ void fma2(ull& d, ull a, ull b) {
    asm("fma.rn.f32x2 %0, %1, %2, %0;" : "+l"(d) : "l"(a), "l"(b));
}
__device__ __forceinline__ float2 unpk(ull v) {
    float2 f; asm("mov.b64 {%0, %1}, %2;" : "=f"(f.x), "=f"(f.y) : "l"(v)); return f;
}
__device__ __forceinline__ float hsig(float x) { return __saturatef(fmaf(0.2f, x, 0.5f)); }

// 16-byte async copy global->shared (LDGSTS), L1-bypass.
__device__ __forceinline__ void cpasync16(unsigned int saddr, const float* g) {
    asm volatile("cp.async.cg.shared.global [%0], [%1], 16;" :: "r"(saddr), "l"(g));
}
__device__ __forceinline__ void cp_commit() {
    asm volatile("cp.async.commit_group;");
}
__device__ __forceinline__ void cp_wait0() {
    asm volatile("cp.async.wait_group 0;");
}

// Load [3 rows][66 cols][64 ch] halo tile transposed to smem [dy][cin][66].
__device__ __forceinline__ void load_tile64(float* __restrict__ s,
                                            const float* __restrict__ frame,
                                            int h, int tid)
{
    for (int idx = tid; idx < 3 * 66 * 16; idx += 256) {
        int c4 = idx & 15;
        int colr = idx >> 4;
        int col = colr % 66;
        int dy = colr / 66;
        int row = h + dy - 1;
        int win = col - 1;
        float4 v = make_float4(0.f, 0.f, 0.f, 0.f);
        if ((unsigned)row < 64u && (unsigned)win < 64u)
            v = *(const float4*)&frame[(row * 64 + win) * 64 + c4 * 4];
        int base = (dy * 64 + c4 * 4) * 66 + col;
        s[base]       = v.x;
        s[base + 66]  = v.y;
        s[base + 132] = v.z;
        s[base + 198] = v.w;
    }
}

// One 3x3 conv contribution with CIN=64: acc += conv(sIn, gw).
// 36 chunks of 16 K-rows; cp.async double-buffered weight staging: prefetch of
// chunk m+1 overlaps compute of chunk m; ONE barrier per chunk. Prefetch into
// buf (m+1)&1 is issued after the iter-m barrier, which orders it against all
// warps' chunk m-1 reads of that same buffer.
// sIn: smem [3][64][66]; gw: global weights [9*64][256] K-major.
// sW: 2 x 4096 floats (double buffer).
__device__ __forceinline__ void conv_part64(ull acc[4][4][2],
                                            const float* __restrict__ sIn,
                                            const float* __restrict__ gw,
                                            float* __restrict__ sW,
                                            int tid, int tw, int n0)
{
    const unsigned int sWa = (unsigned int)__cvta_generic_to_shared(sW);

    // prologue: stage chunk 0 into buf 0
#pragma unroll
    for (int i = 0; i < 4; ++i)
        cpasync16(sWa + (unsigned)(tid + i * 256) * 16u, gw + (tid + i * 256) * 4);
    cp_commit();

    for (int m = 0; m < 36; ++m) {
        cp_wait0();        // chunk m copies done (per-thread)
        __syncthreads();   // visible to all warps; all warps done reading buf (m+1)&1
        if (m + 1 < 36) {
            const unsigned int dst = sWa + (unsigned)(((m + 1) & 1) * 16384);
            const float* src = gw + (m + 1) * 4096;
#pragma unroll
            for (int i = 0; i < 4; ++i)
                cpasync16(dst + (unsigned)(tid + i * 256) * 16u, src + (tid + i * 256) * 4);
            cp_commit();
        }
        const int tap = m >> 2, ch = m & 3;
        const float* sbase = sIn + (tap / 3) * (64 * 66) + (tap % 3);
        const float* wb = sW + (m & 1) * 4096;
#pragma unroll
        for (int kk = 0; kk < 16; ++kk) {
            const float* a = sbase + (ch * 16 + kk) * 66;
            ull aa0 = pack2(a[tw]);
            ull aa1 = pack2(a[tw + 16]);
            ull aa2 = pack2(a[tw + 32]);
            ull aa3 = pack2(a[tw + 48]);
            const float* brow = wb + kk * 256 + n0;
#pragma unroll
            for (int g = 0; g < 4; ++g) {
                ulonglong2 bb = *(const ulonglong2*)(brow + g * 64);
                fma2(acc[0][g][0], aa0, bb.x); fma2(acc[0][g][1], aa0, bb.y);
                fma2(acc[1][g][0], aa1, bb.x); fma2(acc[1][g][1], aa1, bb.y);
                fma2(acc[2][g][0], aa2, bb.x); fma2(acc[2][g][1], aa2, bb.y);
                fma2(acc[3][g][0], aa3, bb.x); fma2(acc[3][g][1], aa3, bb.y);
            }
        }
    }
}

// Fused ConvLSTM step. Block = one (b,h) row: 64 w x 256 gate channels.
// Thread (tn,tw): features n0=4*tn..+3 per gate; w in {tw, tw+16, tw+32, tw+48}.
template <bool CIN1, bool HAS_PREV>
__global__ __launch_bounds__(256)
void step_kernel(const float* __restrict__ xin, long long xin_bstride,
                 const float* __restrict__ hprev,
                 const float* __restrict__ Wx,
                 const float* __restrict__ Wh,
                 const float* __restrict__ bias,
                 float* __restrict__ cbuf,
                 float* __restrict__ hout)
{
    extern __shared__ float smem[];
    constexpr int TILE = (CIN1 && !HAS_PREV) ? 0 : 12672;  // [3][64][66]
    constexpr int SX1  = CIN1 ? 200 : 0;                   // [3][66] + pad (16B align)
    float* sT  = smem;
    float* sX1 = smem + TILE;
    float* sW  = smem + TILE + SX1;                        // 2 x 4096 floats

    const int tid = threadIdx.x;
    const int bh = blockIdx.x;
    const int b = bh >> 6, h = bh & 63;
    const int tn = tid & 15, tw = tid >> 4;
    const int n0 = tn * 4;

    const float* xframe = xin + (long long)b * xin_bstride;

    // ---- load x tile ----
    if constexpr (CIN1) {
        for (int idx = tid; idx < 3 * 66; idx += 256) {
            int dy = idx / 66, col = idx - dy * 66;
            int row = h + dy - 1, win = col - 1;
            float v = 0.f;
            if ((unsigned)row < 64u && (unsigned)win < 64u) v = xframe[row * 64 + win];
            sX1[idx] = v;
        }
    } else {
        load_tile64(sT, xframe, h, tid);
    }

    ull acc[4][4][2];
#pragma unroll
    for (int i = 0; i < 4; i++)
#pragma unroll
        for (int g = 0; g < 4; g++) { acc[i][g][0] = 0ull; acc[i][g][1] = 0ull; }

    // ---- x-conv ----
    if constexpr (CIN1) {
        __syncthreads();
        for (int i = tid; i < 576; i += 256) ((float4*)sW)[i] = ((const float4*)Wx)[i];
        __syncthreads();
#pragma unroll
        for (int tap = 0; tap < 9; ++tap) {
            const float* arow = sX1 + (tap / 3) * 66 + (tap % 3);
            ull aa0 = pack2(arow[tw]);
            ull aa1 = pack2(arow[tw + 16]);
            ull aa2 = pack2(arow[tw + 32]);
            ull aa3 = pack2(arow[tw + 48]);
            const float* brow = sW + tap * 256 + n0;
#pragma unroll
            for (int g = 0; g < 4; ++g) {
                ulonglong2 bb = *(const ulonglong2*)(brow + g * 64);
                fma2(acc[0][g][0], aa0, bb.x); fma2(acc[0][g][1], aa0, bb.y);
                fma2(acc[1][g][0], aa1, bb.x); fma2(acc[1][g][1], aa1, bb.y);
                fma2(acc[2][g][0], aa2, bb.x); fma2(acc[2][g][1], aa2, bb.y);
                fma2(acc[3][g][0], aa3, bb.x); fma2(acc[3][g][1], aa3, bb.y);
            }
        }
    } else {
        __syncthreads();   // sT tile writes ordered before conv's first compute
        conv_part64(acc, sT, Wx, sW, tid, tw, n0);
    }

    // ---- h-conv (reuses sT) ----
    if constexpr (HAS_PREV) {
        __syncthreads();  // x-phase reads of sT/sW complete before overwrite
        load_tile64(sT, hprev + (long long)b * (64 * 64 * 64), h, tid);
        __syncthreads();  // sT ready for all warps before conv compute
        conv_part64(acc, sT, Wh, sW, tid, tw, n0);
    }

    // ---- fused epilogue: bias + activations + state update ----
    float bg[4][4];
#pragma unroll
    for (int g = 0; g < 4; ++g) {
        float4 t = *(const float4*)(bias + g * 64 + n0);
        bg[g][0] = t.x; bg[g][1] = t.y; bg[g][2] = t.z; bg[g][3] = t.w;
    }
    const long long rowbase = (long long)bh * 4096 + n0;
#pragma unroll
    for (int i = 0; i < 4; i++) {
        long long off = rowbase + (long long)(tw + 16 * i) * 64;
        float cp[4] = {0.f, 0.f, 0.f, 0.f};
        if constexpr (HAS_PREV) {
            float4 t = *(const float4*)&cbuf[off];
            cp[0] = t.x; cp[1] = t.y; cp[2] = t.z; cp[3] = t.w;
        }
        float gv[4][4];
#pragma unroll
        for (int g = 0; g < 4; ++g) {
            float2 p0 = unpk(acc[i][g][0]);
            float2 p1 = unpk(acc[i][g][1]);
            gv[g][0] = p0.x + bg[g][0];
            gv[g][1] = p0.y + bg[g][1];
            gv[g][2] = p1.x + bg[g][2];
            gv[g][3] = p1.y + bg[g][3];
        }
        float cn[4], hn[4];
#pragma unroll
        for (int j = 0; j < 4; j++) {
            float iv = hsig(gv[0][j]);
            float fv = hsig(gv[1][j]);
            float gg = tanhf(gv[2][j]);
            float ov = hsig(gv[3][j]);
            float c = fv * cp[j] + iv * gg;
            cn[j] = c;
            hn[j] = ov * tanhf(c);
        }
        *(float4*)&cbuf[off] = make_float4(cn[0], cn[1], cn[2], cn[3]);
        *(float4*)&hout[off] = make_float4(hn[0], hn[1], hn[2], hn[3]);
    }
}

extern "C" void kernel_launch(void* const* d_in, const int* in_sizes, int n_in,
                              void* d_out, int out_size)
{
    const float* x   = (const float*)d_in[0];
    const float* Wx0 = (const float*)d_in[1];
    const float* Wh0 = (const float*)d_in[2];
    const float* b0  = (const float*)d_in[3];
    const float* Wx1 = (const float*)d_in[4];
    const float* Wh1 = (const float*)d_in[5];
    const float* b1  = (const float*)d_in[6];
    float* out = (float*)d_out;

    float *hist0, *hist1, *c0, *c1;
    cudaGetSymbolAddress((void**)&hist0, g_hist0);
    cudaGetSymbolAddress((void**)&hist1, g_hist1);
    cudaGetSymbolAddress((void**)&c0, g_c0);
    cudaGetSymbolAddress((void**)&c1, g_c1);

    const int SM_1N  = (200 + 8192) * 4;                 // 33568 B
    const int SM_1P  = (12672 + 200 + 8192) * 4;         // 84256 B
    const int SM_64N = (12672 + 8192) * 4;               // 83456 B
    const int SM_64P = (12672 + 8192) * 4;               // 83456 B
    cudaFuncSetAttribute(step_kernel<true,  false>, cudaFuncAttributeMaxDynamicSharedMemorySize, SM_1N);
    cudaFuncSetAttribute(step_kernel<true,  true>,  cudaFuncAttributeMaxDynamicSharedMemorySize, SM_1P);
    cudaFuncSetAttribute(step_kernel<false, false>, cudaFuncAttributeMaxDynamicSharedMemorySize, SM_64N);
    cudaFuncSetAttribute(step_kernel<false, true>,  cudaFuncAttributeMaxDynamicSharedMemorySize, SM_64P);

    dim3 grid(512), block(256);

    // Layer 0
    step_kernel<true, false><<<grid, block, SM_1N>>>(x, 40960LL, nullptr,
                                                     Wx0, Wh0, b0, c0, hist0);
    for (int t = 1; t < 10; ++t)
        step_kernel<true, true><<<grid, block, SM_1P>>>(x + (size_t)t * 4096, 40960LL,
                                                        hist0 + (size_t)(t - 1) * FR,
                                                        Wx0, Wh0, b0, c0,
                                                        hist0 + (size_t)t * FR);

    // Layer 1
    step_kernel<false, false><<<grid, block, SM_64N>>>(hist0, 262144LL, nullptr,
                                                       Wx1, Wh1, b1, c1, hist1);
    for (int t = 1; t < 10; ++t)
        step_kernel<false, true><<<grid, block, SM_64P>>>(hist0 + (size_t)t * FR, 262144LL,
                                                          hist1 + (size_t)(t - 1) * FR,
                                                          Wx1, Wh1, b1, c1,
                                                          hist1 + (size_t)t * FR);

    // Pack output: [[h0,c0],[h1,c1]]
    cudaMemcpyAsync(out,              hist0 + 9ull * FR, (size_t)FR * 4, cudaMemcpyDeviceToDevice);
    cudaMemcpyAsync(out + (size_t)FR, c0,                (size_t)FR * 4, cudaMemcpyDeviceToDevice);
    cudaMemcpyAsync(out + 2ull * FR,  hist1 + 9ull * FR, (size_t)FR * 4, cudaMemcpyDeviceToDevice);
    cudaMemcpyAsync(out + 3ull * FR,  c1,                (size_t)FR * 4, cudaMemcpyDeviceToDevice);
}